// round 2
// baseline (speedup 1.0000x reference)
#include <cuda_runtime.h>
#include <math.h>

// LatentRNN: B=2048, T=512, P=8, L=64, H=180
// 128 persistent CTAs x 16 batch rows; all per-step state in SMEM; fp32 SIMT.

#define B_   2048
#define T_   512
#define P_   8
#define L_   64
#define H_   180
#define IN_K 72        // P_ + L_
#define CAT_K 244      // H_ + L_
#define BT   16
#define NTHR 384

struct __align__(16) Smem {
    float inT [IN_K ][BT];     // [phys_t ; cur] transposed (also latents for h0)
    float xT  [H_   ][BT];     // gelu(in @ W_in^T) transposed
    float hT  [2][H_][BT];     // hidden state, double buffered, transposed
    float giT [3*H_ ][BT];     // x @ W_ih^T + b_ih
    float ghT [3*H_ ][BT];     // h @ W_hh^T + b_hh
    float catT[CAT_K][BT];     // [h_new ; cur] transposed
    float oT  [H_   ][BT];     // gelu(W_o1 @ hcat) transposed
    float cur [BT][L_];        // current latent state
};

__device__ __forceinline__ float gelu_f(float v) {
    return 0.5f * v * (1.0f + erff(v * 0.70710678118654752440f));
}
__device__ __forceinline__ float sigmoid_f(float v) {
    return 1.0f / (1.0f + expf(-v));
}

// One output column, 16 batch rows in registers. Activation reads are
// warp-uniform SMEM loads (broadcast); weight row read as float4 along K.
__device__ __forceinline__ void colgemm(const float* __restrict__ w, int K,
                                        const float (*__restrict__ in)[BT],
                                        float* __restrict__ acc) {
#pragma unroll 4
    for (int k = 0; k < K; k += 4) {
        float4 wv = *(const float4*)(w + k);
        float wa[4] = {wv.x, wv.y, wv.z, wv.w};
#pragma unroll
        for (int kk = 0; kk < 4; kk++) {
            const float4* xr = (const float4*)(in[k + kk]);
            float4 a = xr[0], b = xr[1], c = xr[2], d = xr[3];
            float w0 = wa[kk];
            acc[0]  += a.x * w0; acc[1]  += a.y * w0; acc[2]  += a.z * w0; acc[3]  += a.w * w0;
            acc[4]  += b.x * w0; acc[5]  += b.y * w0; acc[6]  += b.z * w0; acc[7]  += b.w * w0;
            acc[8]  += c.x * w0; acc[9]  += c.y * w0; acc[10] += c.z * w0; acc[11] += c.w * w0;
            acc[12] += d.x * w0; acc[13] += d.y * w0; acc[14] += d.z * w0; acc[15] += d.w * w0;
        }
    }
}

__global__ __launch_bounds__(NTHR, 1)
void latent_rnn_kernel(const float* __restrict__ phys,
                       const float* __restrict__ latents,
                       const float* __restrict__ W_in, const float* __restrict__ b_in,
                       const float* __restrict__ W_hp, const float* __restrict__ b_hp,
                       const float* __restrict__ W_ih, const float* __restrict__ b_ih,
                       const float* __restrict__ W_hh, const float* __restrict__ b_hh,
                       const float* __restrict__ W_o1, const float* __restrict__ b_o1,
                       const float* __restrict__ W_o2, const float* __restrict__ b_o2,
                       float* __restrict__ out)
{
    extern __shared__ char smem_raw[];
    Smem* s = reinterpret_cast<Smem*>(smem_raw);
    const int tid = threadIdx.x;
    const int b0  = blockIdx.x * BT;

    // ---- init: cur = latents; stage latents^T for the h0 GEMM ----
    for (int i = tid; i < BT * L_; i += NTHR) {
        int r = i >> 6, l = i & 63;
        float v = latents[(b0 + r) * L_ + l];
        s->cur[r][l] = v;
        s->inT[l][r] = v;
    }
    __syncthreads();

    // ---- h0 = latents @ W_hp^T + b_hp ----
    for (int j = tid; j < H_; j += NTHR) {
        float acc[BT];
#pragma unroll
        for (int r = 0; r < BT; r++) acc[r] = 0.f;
        colgemm(W_hp + j * L_, L_, s->inT, acc);
        float bb = b_hp[j];
#pragma unroll
        for (int r = 0; r < BT; r++) s->hT[0][j][r] = acc[r] + bb;
    }
    __syncthreads();

    for (int t = 0; t < T_; t++) {
        const int cb = t & 1, nb = cb ^ 1;

        // ---- A: inT = [phys_t ; cur] transposed ----
        for (int i = tid; i < BT * IN_K; i += NTHR) {
            int r = i / IN_K, k = i - r * IN_K;
            float v = (k < P_) ? phys[((size_t)(b0 + r) * T_ + t) * P_ + k]
                               : s->cur[r][k - P_];
            s->inT[k][r] = v;
        }
        __syncthreads();

        // ---- B: xT = gelu(inT @ W_in^T + b_in) ----
        for (int j = tid; j < H_; j += NTHR) {
            float acc[BT];
#pragma unroll
            for (int r = 0; r < BT; r++) acc[r] = 0.f;
            colgemm(W_in + j * IN_K, IN_K, s->inT, acc);
            float bb = b_in[j];
#pragma unroll
            for (int r = 0; r < BT; r++) s->xT[j][r] = gelu_f(acc[r] + bb);
        }
        __syncthreads();

        // ---- C: gi = x @ W_ih^T + b_ih ; gh = h @ W_hh^T + b_hh  (1080 col-tasks) ----
        for (int i = tid; i < 6 * H_; i += NTHR) {
            int mat = (i >= 3 * H_);
            int j   = mat ? i - 3 * H_ : i;
            const float* w = (mat ? W_hh : W_ih) + j * H_;
            const float (*inp)[BT] = mat ? s->hT[cb] : s->xT;
            float acc[BT];
#pragma unroll
            for (int r = 0; r < BT; r++) acc[r] = 0.f;
            colgemm(w, H_, inp, acc);
            float bb = (mat ? b_hh : b_ih)[j];
            float* o = mat ? s->ghT[j] : s->giT[j];
#pragma unroll
            for (int r = 0; r < BT; r++) o[r] = acc[r] + bb;
        }
        __syncthreads();

        // ---- gates: h_new, build catT ----
        for (int i = tid; i < H_ * BT; i += NTHR) {
            int j = i >> 4, r = i & 15;
            float rg = sigmoid_f(s->giT[j       ][r] + s->ghT[j       ][r]);
            float zg = sigmoid_f(s->giT[j +   H_][r] + s->ghT[j +   H_][r]);
            float ng = tanhf    (s->giT[j + 2*H_][r] + rg * s->ghT[j + 2*H_][r]);
            float hn = (1.f - zg) * ng + zg * s->hT[cb][j][r];
            s->hT[nb][j][r] = hn;
            s->catT[j][r]   = hn;
        }
        for (int i = tid; i < L_ * BT; i += NTHR) {
            int l = i >> 4, r = i & 15;
            s->catT[H_ + l][r] = s->cur[r][l];
        }
        __syncthreads();

        // ---- D: oT = gelu(catT @ W_o1^T + b_o1) ----
        for (int j = tid; j < H_; j += NTHR) {
            float acc[BT];
#pragma unroll
            for (int r = 0; r < BT; r++) acc[r] = 0.f;
            colgemm(W_o1 + j * CAT_K, CAT_K, s->catT, acc);
            float bb = b_o1[j];
#pragma unroll
            for (int r = 0; r < BT; r++) s->oT[j][r] = gelu_f(acc[r] + bb);
        }
        __syncthreads();

        // ---- E: delta = oT @ W_o2^T + b_o2 ; cur = clip(cur + delta); store ----
        for (int j = tid; j < L_; j += NTHR) {   // threads 0..63
            float acc[BT];
#pragma unroll
            for (int r = 0; r < BT; r++) acc[r] = 0.f;
            colgemm(W_o2 + j * H_, H_, s->oT, acc);
            float bb = b_o2[j];
#pragma unroll
            for (int r = 0; r < BT; r++) {
                float c = s->cur[r][j] + acc[r] + bb;
                c = fminf(fmaxf(c, 0.f), 1.f);
                s->cur[r][j] = c;
                out[((size_t)(b0 + r) * T_ + t) * L_ + j] = c;
            }
        }
        __syncthreads();
    }
}

extern "C" void kernel_launch(void* const* d_in, const int* in_sizes, int n_in,
                              void* d_out, int out_size)
{
    const float* phys    = (const float*)d_in[0];
    const float* latents = (const float*)d_in[1];
    const float* W_in    = (const float*)d_in[2];
    const float* b_in    = (const float*)d_in[3];
    const float* W_hp    = (const float*)d_in[4];
    const float* b_hp    = (const float*)d_in[5];
    const float* W_ih    = (const float*)d_in[6];
    const float* b_ih    = (const float*)d_in[7];
    const float* W_hh    = (const float*)d_in[8];
    const float* b_hh    = (const float*)d_in[9];
    const float* W_o1    = (const float*)d_in[10];
    const float* b_o1    = (const float*)d_in[11];
    const float* W_o2    = (const float*)d_in[12];
    const float* b_o2    = (const float*)d_in[13];
    float* out = (float*)d_out;

    static bool attr_set = false;
    if (!attr_set) {
        cudaFuncSetAttribute(latent_rnn_kernel,
                             cudaFuncAttributeMaxDynamicSharedMemorySize,
                             (int)sizeof(Smem));
        attr_set = true;
    }

    latent_rnn_kernel<<<B_ / BT, NTHR, sizeof(Smem)>>>(
        phys, latents, W_in, b_in, W_hp, b_hp, W_ih, b_ih, W_hh, b_hh,
        W_o1, b_o1, W_o2, b_o2, out);
}